// round 11
// baseline (speedup 1.0000x reference)
#include <cuda_runtime.h>
#include <cuda_bf16.h>
#include <math.h>
#include <stdint.h>

// Problem constants
#define BATCH 4
#define SEQ   2048
#define EMB   1024
#define MTOT  (BATCH * SEQ)   // 8192

typedef __nv_bfloat16 bf16;

// ---------------------------------------------------------------------------
// Scratch (static device globals)
// ---------------------------------------------------------------------------
__device__ bf16 g_xh[(size_t)MTOT * EMB],  g_xl[(size_t)MTOT * EMB];
__device__ bf16 g_Wqh[(size_t)EMB * EMB],  g_Wql[(size_t)EMB * EMB];
__device__ bf16 g_Wkh[(size_t)EMB * EMB],  g_Wkl[(size_t)EMB * EMB];
__device__ bf16 g_Wvh[(size_t)EMB * EMB],  g_Wvl[(size_t)EMB * EMB];
__device__ bf16 g_Qh[(size_t)MTOT * EMB],  g_Ql[(size_t)MTOT * EMB];
__device__ bf16 g_Kh[(size_t)MTOT * EMB],  g_Kl[(size_t)MTOT * EMB];
__device__ bf16 g_Vth[(size_t)EMB * MTOT], g_Vtl[(size_t)EMB * MTOT]; // transposed [e][m]
__device__ float g_S[(size_t)BATCH * SEQ * SEQ];
__device__ bf16 g_Ph[(size_t)BATCH * SEQ * SEQ], g_Pl[(size_t)BATCH * SEQ * SEQ];

// ---------------------------------------------------------------------------
// helpers
// ---------------------------------------------------------------------------
__device__ __forceinline__ void mma_bf16(float* c, const unsigned* a, const unsigned* b) {
    asm("mma.sync.aligned.m16n8k16.row.col.f32.bf16.bf16.f32 "
        "{%0,%1,%2,%3},{%4,%5,%6,%7},{%8,%9},{%0,%1,%2,%3};"
        : "+f"(c[0]), "+f"(c[1]), "+f"(c[2]), "+f"(c[3])
        : "r"(a[0]), "r"(a[1]), "r"(a[2]), "r"(a[3]), "r"(b[0]), "r"(b[1]));
}
__device__ __forceinline__ void ldm_x4(unsigned* r, uint32_t addr) {
    asm volatile("ldmatrix.sync.aligned.m8n8.x4.shared.b16 {%0,%1,%2,%3}, [%4];"
                 : "=r"(r[0]), "=r"(r[1]), "=r"(r[2]), "=r"(r[3]) : "r"(addr));
}
__device__ __forceinline__ void cp16(uint32_t dst, const void* src) {
    asm volatile("cp.async.cg.shared.global [%0], [%1], 16;" :: "r"(dst), "l"(src) : "memory");
}
#define CP_COMMIT() asm volatile("cp.async.commit_group;" ::: "memory")
#define CP_WAIT2()  asm volatile("cp.async.wait_group 2;" ::: "memory")

// ---------------------------------------------------------------------------
// SMEM: 3 stages x 4 arrays (Ah,Al,Bh,Bl) x [128][40] bf16.
// Padded rows (40 halves = 80B) keep ldmatrix conflict-free (proven in R7).
// ---------------------------------------------------------------------------
#define NS 3
#define BKP 40
#define ARR_B (128 * BKP * 2)          // 10240 bytes per array
#define STG_B (4 * ARR_B)              // 40960 bytes per stage
#define SMEM_TOT (NS * STG_B)          // 122880 bytes

// ---------------------------------------------------------------------------
// NT GEMM via bf16-split mma.sync (3 passes hh+lh+hl), fp32 accumulate.
// Operands PRE-SPLIT bf16 hi/lo in gmem; cp.async 3-stage pipeline.
//   C[M,N] = (Ah+Al)[M,K] * (Bh+Bl)[N,K]^T
// 128x128 tile, BK=32, 256 threads = 8 warps (2M x 4N), warp tile 64x32.
// mode 0: bf16 hi/lo out + bias            (Q/K projection)
// mode 1: fp32 out * 1/32, skip n0 > m0    (causal scores)
// mode 2: fp32 out, k bounded at m0+128    (PV)
// mode 3: transposed bf16 hi/lo out + bias (V projection -> Vt)
// ---------------------------------------------------------------------------
__global__ void __launch_bounds__(256)
mma_gemm_nt(const bf16* __restrict__ Ah, const bf16* __restrict__ Al,
            const bf16* __restrict__ Bh, const bf16* __restrict__ Bl,
            float* __restrict__ Cf, bf16* __restrict__ Chi, bf16* __restrict__ Clo,
            const float* __restrict__ bias,
            int lda, int ldb, int ldc, int kdim, int mode,
            size_t sA, size_t sB, size_t sC)
{
    extern __shared__ __align__(16) unsigned char smem[];

    const int bz = blockIdx.z;
    Ah += (size_t)bz * sA;  Al += (size_t)bz * sA;
    Bh += (size_t)bz * sB;  Bl += (size_t)bz * sB;
    if (Cf)  Cf  += (size_t)bz * sC;
    if (Chi) { Chi += (size_t)bz * sC; Clo += (size_t)bz * sC; }

    const int m0 = blockIdx.y * 128;
    const int n0 = blockIdx.x * 128;
    if (mode == 1 && n0 > m0) return;          // strictly-upper causal block

    int kmax = kdim;
    if (mode == 2) { int kb = m0 + 128; kmax = kb < kdim ? kb : kdim; }
    const int NT = kmax >> 5;                  // chunks of K=32 (NT >= 4 always)

    const int tid  = threadIdx.x;
    const int lane = tid & 31;
    const int w    = tid >> 5;
    const int warpM = (w >> 2) * 64;
    const int warpN = (w & 3) * 32;
    const int g  = lane >> 2;
    const int c2 = (lane & 3) << 1;

    const uint32_t sbase = (uint32_t)__cvta_generic_to_shared(smem);
    // ldmatrix per-lane byte offsets within one array (validated in R7)
    const uint32_t laneA = (uint32_t)(((warpM + ((lane >> 3) & 1) * 8 + (lane & 7)) * BKP
                                      + (lane >> 4) * 8) * 2);
    const uint32_t laneB = (uint32_t)(((warpN + ((lane >> 3) >> 1) * 8 + (lane & 7)) * BKP
                                      + ((lane >> 3) & 1) * 8) * 2);

    const bf16* srcs[4] = { Ah, Al, Bh, Bl };
    const int   lds [4] = { lda, lda, ldb, ldb };
    const int   rbs [4] = { m0, m0, n0, n0 };

    // per-thread copy coords: 2 x 16B units per array per chunk
    const int crow = tid >> 2;                 // 0..63? no: tid+u*256 below
    (void)crow;

    auto fill = [&](int s, int k0) {
#pragma unroll
        for (int arr = 0; arr < 4; ++arr) {
            const bf16* S = srcs[arr];
            const int ld = lds[arr], rb = rbs[arr];
            const uint32_t dbase = sbase + (uint32_t)(s * STG_B + arr * ARR_B);
#pragma unroll
            for (int u = 0; u < 2; ++u) {
                int idx = tid + u * 256;       // 512 units per array
                int r = idx >> 2, q = idx & 3; // row, 16B-quarter (8 halves)
                cp16(dbase + (uint32_t)((r * BKP + q * 8) * 2),
                     S + (size_t)(rb + r) * ld + k0 + q * 8);
            }
        }
    };

    float acc[4][4][4];
#pragma unroll
    for (int mt = 0; mt < 4; ++mt)
#pragma unroll
        for (int nt = 0; nt < 4; ++nt)
#pragma unroll
            for (int r = 0; r < 4; ++r) acc[mt][nt][r] = 0.0f;

    // prefetch NS-1 stages
    int fetch = 0;
#pragma unroll
    for (int p = 0; p < NS - 1; ++p) {
        if (fetch < NT) fill(fetch % NS, fetch << 5);
        CP_COMMIT();
        ++fetch;
    }

    for (int it = 0; it < NT; ++it) {
        __syncthreads();                       // all warps done with stage it-1
        if (fetch < NT) fill(fetch % NS, fetch << 5);
        CP_COMMIT();
        ++fetch;
        CP_WAIT2();                            // stage it's group complete
        __syncthreads();                       // visible to all warps

        const int s = it % NS;
        const uint32_t aHi = sbase + (uint32_t)(s * STG_B) + laneA;
        const uint32_t aLo = aHi + ARR_B;
        const uint32_t bHi = sbase + (uint32_t)(s * STG_B + 2 * ARR_B) + laneB;
        const uint32_t bLo = bHi + ARR_B;

#pragma unroll
        for (int ks = 0; ks < 2; ++ks) {
            const uint32_t kboff = (uint32_t)(ks * 16 * 2);
            unsigned ah[4][4], bh[4][2], al[4][4], bl[4][2];
#pragma unroll
            for (int mt = 0; mt < 4; ++mt)
                ldm_x4(ah[mt], aHi + (uint32_t)(mt * 16 * BKP * 2) + kboff);
#pragma unroll
            for (int p = 0; p < 2; ++p) {
                unsigned t[4];
                ldm_x4(t, bHi + (uint32_t)(p * 16 * BKP * 2) + kboff);
                bh[2 * p][0] = t[0]; bh[2 * p][1] = t[1];
                bh[2 * p + 1][0] = t[2]; bh[2 * p + 1][1] = t[3];
            }
#pragma unroll
            for (int mt = 0; mt < 4; ++mt)
#pragma unroll
                for (int nt = 0; nt < 4; ++nt)
                    mma_bf16(acc[mt][nt], ah[mt], bh[nt]);

#pragma unroll
            for (int mt = 0; mt < 4; ++mt)
                ldm_x4(al[mt], aLo + (uint32_t)(mt * 16 * BKP * 2) + kboff);
#pragma unroll
            for (int mt = 0; mt < 4; ++mt)
#pragma unroll
                for (int nt = 0; nt < 4; ++nt)
                    mma_bf16(acc[mt][nt], al[mt], bh[nt]);

#pragma unroll
            for (int p = 0; p < 2; ++p) {
                unsigned t[4];
                ldm_x4(t, bLo + (uint32_t)(p * 16 * BKP * 2) + kboff);
                bl[2 * p][0] = t[0]; bl[2 * p][1] = t[1];
                bl[2 * p + 1][0] = t[2]; bl[2 * p + 1][1] = t[3];
            }
#pragma unroll
            for (int mt = 0; mt < 4; ++mt)
#pragma unroll
                for (int nt = 0; nt < 4; ++nt)
                    mma_bf16(acc[mt][nt], ah[mt], bl[nt]);
        }
    }

    // ---- epilogue ----
    const float scale = (mode == 1) ? 0.03125f : 1.0f;
#pragma unroll
    for (int mt = 0; mt < 4; ++mt) {
        const int mr = m0 + warpM + mt * 16 + g;
#pragma unroll
        for (int nt = 0; nt < 4; ++nt) {
            const int nc = n0 + warpN + nt * 8 + c2;
            float* cc = acc[mt][nt];
            if (mode == 3) {                   // transposed bf16 hi/lo + bias (Vt)
                float b0 = bias[nc], b1 = bias[nc + 1];
                float v00 = cc[0] + b0, v01 = cc[1] + b1;
                float v10 = cc[2] + b0, v11 = cc[3] + b1;
                bf16 h00 = __float2bfloat16_rn(v00), h01 = __float2bfloat16_rn(v01);
                bf16 h10 = __float2bfloat16_rn(v10), h11 = __float2bfloat16_rn(v11);
                size_t o0 = (size_t)nc * ldc + mr, o1 = (size_t)(nc + 1) * ldc + mr;
                Chi[o0] = h00;      Chi[o1] = h01;
                Chi[o0 + 8] = h10;  Chi[o1 + 8] = h11;
                Clo[o0]     = __float2bfloat16_rn(v00 - __bfloat162float(h00));
                Clo[o1]     = __float2bfloat16_rn(v01 - __bfloat162float(h01));
                Clo[o0 + 8] = __float2bfloat16_rn(v10 - __bfloat162float(h10));
                Clo[o1 + 8] = __float2bfloat16_rn(v11 - __bfloat162float(h11));
            } else if (mode == 0) {            // bf16 hi/lo + bias
                float b0 = bias[nc], b1 = bias[nc + 1];
                float v00 = cc[0] + b0, v01 = cc[1] + b1;
                float v10 = cc[2] + b0, v11 = cc[3] + b1;
                __nv_bfloat162 h0 = __floats2bfloat162_rn(v00, v01);
                __nv_bfloat162 h1 = __floats2bfloat162_rn(v10, v11);
                size_t o0 = (size_t)mr * ldc + nc, o1 = (size_t)(mr + 8) * ldc + nc;
                *(__nv_bfloat162*)&Chi[o0] = h0;
                *(__nv_bfloat162*)&Chi[o1] = h1;
                __nv_bfloat162 l0 = __floats2bfloat162_rn(v00 - __bfloat162float(h0.x),
                                                          v01 - __bfloat162float(h0.y));
                __nv_bfloat162 l1 = __floats2bfloat162_rn(v10 - __bfloat162float(h1.x),
                                                          v11 - __bfloat162float(h1.y));
                *(__nv_bfloat162*)&Clo[o0] = l0;
                *(__nv_bfloat162*)&Clo[o1] = l1;
            } else {                           // fp32 (mode 1 scaled, mode 2 plain)
                *(float2*)&Cf[(size_t)mr * ldc + nc] =
                    make_float2(cc[0] * scale, cc[1] * scale);
                *(float2*)&Cf[(size_t)(mr + 8) * ldc + nc] =
                    make_float2(cc[2] * scale, cc[3] * scale);
            }
        }
    }
}

// ---------------------------------------------------------------------------
// fp32 -> bf16 hi/lo split (elementwise, vectorized by 4)
// ---------------------------------------------------------------------------
__global__ void __launch_bounds__(256)
cvt_split(const float* __restrict__ x, bf16* __restrict__ hi, bf16* __restrict__ lo, int n4)
{
    int i = blockIdx.x * 256 + threadIdx.x;
    if (i >= n4) return;
    float4 v = ((const float4*)x)[i];
    float a[4] = { v.x, v.y, v.z, v.w };
    bf16 h[4]; bf16 l[4];
#pragma unroll
    for (int e = 0; e < 4; ++e) {
        h[e] = __float2bfloat16_rn(a[e]);
        l[e] = __float2bfloat16_rn(a[e] - __bfloat162float(h[e]));
    }
    ((ushort4*)hi)[i] = make_ushort4(*(unsigned short*)&h[0], *(unsigned short*)&h[1],
                                     *(unsigned short*)&h[2], *(unsigned short*)&h[3]);
    ((ushort4*)lo)[i] = make_ushort4(*(unsigned short*)&l[0], *(unsigned short*)&l[1],
                                     *(unsigned short*)&l[2], *(unsigned short*)&l[3]);
}

// ---------------------------------------------------------------------------
// Causal row softmax: reads S fp32, writes P as bf16 hi/lo (zeros in masked
// tail of the diagonal block so PV needs no per-element mask).
// ---------------------------------------------------------------------------
__global__ void __launch_bounds__(256)
softmax_kernel(const float* __restrict__ Sc, bf16* __restrict__ Ph, bf16* __restrict__ Pl)
{
    const int row = blockIdx.x;
    const int q   = row & (SEQ - 1);
    const float* r = Sc + (size_t)row * SEQ;
    const int kend = ((q >> 7) + 1) << 7;
    const int tid = threadIdx.x;

    float vals[8];
    float mx = -INFINITY;
    {
        int it = 0;
        for (int j = tid; j < kend; j += 256, ++it) {
            float v = (j <= q) ? r[j] : -INFINITY;
            vals[it] = v;
            mx = fmaxf(mx, v);
        }
    }

    __shared__ float red[8];
#pragma unroll
    for (int o = 16; o > 0; o >>= 1) mx = fmaxf(mx, __shfl_xor_sync(0xffffffffu, mx, o));
    if ((tid & 31) == 0) red[tid >> 5] = mx;
    __syncthreads();
    if (tid == 0) {
        float m = red[0];
#pragma unroll
        for (int i = 1; i < 8; ++i) m = fmaxf(m, red[i]);
        red[0] = m;
    }
    __syncthreads();
    mx = red[0];
    __syncthreads();

    float sum = 0.0f;
    {
        int it = 0;
        for (int j = tid; j < kend; j += 256, ++it) {
            float e = __expf(vals[it] - mx);
            vals[it] = e;
            sum += e;
        }
    }
#pragma unroll
    for (int o = 16; o > 0; o >>= 1) sum += __shfl_xor_sync(0xffffffffu, sum, o);
    if ((tid & 31) == 0) red[tid >> 5] = sum;
    __syncthreads();
    if (tid == 0) {
        float s = red[0];
#pragma unroll
        for (int i = 1; i < 8; ++i) s += red[i];
        red[0] = s;
    }
    __syncthreads();
    const float inv = 1.0f / red[0];

    {
        bf16* ph = Ph + (size_t)row * SEQ;
        bf16* pl = Pl + (size_t)row * SEQ;
        int it = 0;
        for (int j = tid; j < kend; j += 256, ++it) {
            float p = vals[it] * inv;
            bf16 h = __float2bfloat16_rn(p);
            ph[j] = h;
            pl[j] = __float2bfloat16_rn(p - __bfloat162float(h));
        }
    }
}

// ---------------------------------------------------------------------------
// Launch. Inputs: x, Wq, bq, Wk, bk, Wv, bv, mask (mask = known tril, ignored).
// ---------------------------------------------------------------------------
extern "C" void kernel_launch(void* const* d_in, const int* in_sizes, int n_in,
                              void* d_out, int out_size)
{
    const float* x  = (const float*)d_in[0];
    const float* Wq = (const float*)d_in[1];
    const float* bq = (const float*)d_in[2];
    const float* Wk = (const float*)d_in[3];
    const float* bk = (const float*)d_in[4];
    const float* Wv = (const float*)d_in[5];
    const float* bv = (const float*)d_in[6];
    float* out = (float*)d_out;

    bf16 *xh, *xl, *Wqh, *Wql, *Wkh, *Wkl, *Wvh, *Wvl;
    bf16 *Qh, *Ql, *Kh, *Kl, *Vth, *Vtl, *Ph, *Pl;
    float *Sc;
    cudaGetSymbolAddress((void**)&xh,  g_xh);   cudaGetSymbolAddress((void**)&xl,  g_xl);
    cudaGetSymbolAddress((void**)&Wqh, g_Wqh);  cudaGetSymbolAddress((void**)&Wql, g_Wql);
    cudaGetSymbolAddress((void**)&Wkh, g_Wkh);  cudaGetSymbolAddress((void**)&Wkl, g_Wkl);
    cudaGetSymbolAddress((void**)&Wvh, g_Wvh);  cudaGetSymbolAddress((void**)&Wvl, g_Wvl);
    cudaGetSymbolAddress((void**)&Qh,  g_Qh);   cudaGetSymbolAddress((void**)&Ql,  g_Ql);
    cudaGetSymbolAddress((void**)&Kh,  g_Kh);   cudaGetSymbolAddress((void**)&Kl,  g_Kl);
    cudaGetSymbolAddress((void**)&Vth, g_Vth);  cudaGetSymbolAddress((void**)&Vtl, g_Vtl);
    cudaGetSymbolAddress((void**)&Ph,  g_Ph);   cudaGetSymbolAddress((void**)&Pl,  g_Pl);
    cudaGetSymbolAddress((void**)&Sc,  g_S);

    cudaFuncSetAttribute(mma_gemm_nt, cudaFuncAttributeMaxDynamicSharedMemorySize, SMEM_TOT);

    dim3 blk(256);

    // 0) split fp32 -> bf16 hi/lo for x and weights
    cvt_split<<<(MTOT * EMB / 4 + 255) / 256, blk>>>(x,  xh,  xl,  MTOT * EMB / 4);
    cvt_split<<<(EMB * EMB / 4 + 255) / 256, blk>>>(Wq, Wqh, Wql, EMB * EMB / 4);
    cvt_split<<<(EMB * EMB / 4 + 255) / 256, blk>>>(Wk, Wkh, Wkl, EMB * EMB / 4);
    cvt_split<<<(EMB * EMB / 4 + 255) / 256, blk>>>(Wv, Wvh, Wvl, EMB * EMB / 4);

    // 1) QKV projections (NT): Q,K -> bf16 hi/lo; V -> transposed bf16 hi/lo
    dim3 gQKV(EMB / 128, MTOT / 128, 1);
    mma_gemm_nt<<<gQKV, blk, SMEM_TOT>>>(xh, xl, Wqh, Wql, nullptr, Qh, Ql, bq,
                                         EMB, EMB, EMB, EMB, 0, 0, 0, 0);
    mma_gemm_nt<<<gQKV, blk, SMEM_TOT>>>(xh, xl, Wkh, Wkl, nullptr, Kh, Kl, bk,
                                         EMB, EMB, EMB, EMB, 0, 0, 0, 0);
    mma_gemm_nt<<<gQKV, blk, SMEM_TOT>>>(xh, xl, Wvh, Wvl, nullptr, Vth, Vtl, bv,
                                         EMB, EMB, MTOT, EMB, 3, 0, 0, 0);

    // 2) scores = Q K^T / 32 (NT, causal skip, batched)
    dim3 gS(SEQ / 128, SEQ / 128, BATCH);
    mma_gemm_nt<<<gS, blk, SMEM_TOT>>>(Qh, Ql, Kh, Kl, Sc, nullptr, nullptr, nullptr,
                                       EMB, EMB, SEQ, EMB, 1,
                                       (size_t)SEQ * EMB, (size_t)SEQ * EMB, (size_t)SEQ * SEQ);

    // 3) causal softmax -> P bf16 hi/lo
    softmax_kernel<<<BATCH * SEQ, blk>>>(Sc, Ph, Pl);

    // 4) out = P V  (NT against Vt, k-bounded, batched)
    dim3 gPV(EMB / 128, SEQ / 128, BATCH);
    mma_gemm_nt<<<gPV, blk, SMEM_TOT>>>(Ph, Pl, Vth, Vtl, out, nullptr, nullptr, nullptr,
                                        SEQ, MTOT, EMB, SEQ, 2,
                                        (size_t)SEQ * SEQ, (size_t)SEQ, (size_t)SEQ * EMB);
}

// round 12
// speedup vs baseline: 1.1945x; 1.1945x over previous
#include <cuda_runtime.h>
#include <cuda_bf16.h>
#include <math.h>
#include <stdint.h>

// Problem constants
#define BATCH 4
#define SEQ   2048
#define EMB   1024
#define MTOT  (BATCH * SEQ)   // 8192

typedef __nv_bfloat16 bf16;

// ---------------------------------------------------------------------------
// Scratch (static device globals)
// ---------------------------------------------------------------------------
__device__ bf16 g_xh[(size_t)MTOT * EMB],  g_xl[(size_t)MTOT * EMB];
__device__ bf16 g_Wqh[(size_t)EMB * EMB],  g_Wql[(size_t)EMB * EMB];
__device__ bf16 g_Wkh[(size_t)EMB * EMB],  g_Wkl[(size_t)EMB * EMB];
__device__ bf16 g_Wvh[(size_t)EMB * EMB],  g_Wvl[(size_t)EMB * EMB];
__device__ bf16 g_Qh[(size_t)MTOT * EMB],  g_Ql[(size_t)MTOT * EMB];
__device__ bf16 g_Kh[(size_t)MTOT * EMB],  g_Kl[(size_t)MTOT * EMB];
__device__ bf16 g_Vth[(size_t)EMB * MTOT], g_Vtl[(size_t)EMB * MTOT]; // transposed [e][m]
__device__ float g_S[(size_t)BATCH * SEQ * SEQ];
__device__ bf16 g_Ph[(size_t)BATCH * SEQ * SEQ], g_Pl[(size_t)BATCH * SEQ * SEQ];

// ---------------------------------------------------------------------------
// helpers
// ---------------------------------------------------------------------------
__device__ __forceinline__ void mma_bf16(float* c, const unsigned* a, const unsigned* b) {
    asm("mma.sync.aligned.m16n8k16.row.col.f32.bf16.bf16.f32 "
        "{%0,%1,%2,%3},{%4,%5,%6,%7},{%8,%9},{%0,%1,%2,%3};"
        : "+f"(c[0]), "+f"(c[1]), "+f"(c[2]), "+f"(c[3])
        : "r"(a[0]), "r"(a[1]), "r"(a[2]), "r"(a[3]), "r"(b[0]), "r"(b[1]));
}
__device__ __forceinline__ void ldm_x4(unsigned* r, uint32_t addr) {
    asm volatile("ldmatrix.sync.aligned.m8n8.x4.shared.b16 {%0,%1,%2,%3}, [%4];"
                 : "=r"(r[0]), "=r"(r[1]), "=r"(r[2]), "=r"(r[3]) : "r"(addr));
}

// ---------------------------------------------------------------------------
// SMEM: 2 stages x 4 arrays (Ah,Al,Bh,Bl) x [128][40] bf16 = 81920 bytes.
// Padded rows (40 halves = 80B) keep ldmatrix conflict-free (proven in R7).
// ---------------------------------------------------------------------------
#define BKP 40
#define ARR_B (128 * BKP * 2)          // 10240 bytes per array
#define STG_B (4 * ARR_B)              // 40960 bytes per stage
#define SMEM_TOT (2 * STG_B)           // 81920 bytes

// ---------------------------------------------------------------------------
// NT GEMM via bf16-split mma.sync (3 passes hh+lh+hl), fp32 accumulate.
// Operands PRE-SPLIT bf16 hi/lo in gmem. R7-proven schedule: register
// prefetch overlapping compute, double-buffered smem, ONE sync per chunk.
//   C[M,N] = (Ah+Al)[M,K] * (Bh+Bl)[N,K]^T
// 128x128 tile, BK=32, 256 threads = 8 warps (2M x 4N), warp tile 64x32.
// mode 0: bf16 hi/lo out + bias            (Q/K projection)
// mode 1: fp32 out * 1/32, skip n0 > m0    (causal scores)
// mode 2: fp32 out, k bounded at m0+128    (PV)
// mode 3: transposed bf16 hi/lo out + bias (V projection -> Vt)
// ---------------------------------------------------------------------------
__global__ void __launch_bounds__(256)
mma_gemm_nt(const bf16* __restrict__ Ah, const bf16* __restrict__ Al,
            const bf16* __restrict__ Bh, const bf16* __restrict__ Bl,
            float* __restrict__ Cf, bf16* __restrict__ Chi, bf16* __restrict__ Clo,
            const float* __restrict__ bias,
            int lda, int ldb, int ldc, int kdim, int mode,
            size_t sA, size_t sB, size_t sC)
{
    extern __shared__ __align__(16) unsigned char smem[];

    const int bz = blockIdx.z;
    Ah += (size_t)bz * sA;  Al += (size_t)bz * sA;
    Bh += (size_t)bz * sB;  Bl += (size_t)bz * sB;
    if (Cf)  Cf  += (size_t)bz * sC;
    if (Chi) { Chi += (size_t)bz * sC; Clo += (size_t)bz * sC; }

    const int m0 = blockIdx.y * 128;
    const int n0 = blockIdx.x * 128;
    if (mode == 1 && n0 > m0) return;          // strictly-upper causal block

    int kmax = kdim;
    if (mode == 2) { int kb = m0 + 128; kmax = kb < kdim ? kb : kdim; }
    const int NT = kmax >> 5;                  // chunks of K=32 (NT >= 4 always)

    const int tid  = threadIdx.x;
    const int lane = tid & 31;
    const int w    = tid >> 5;
    const int warpM = (w >> 2) * 64;
    const int warpN = (w & 3) * 32;
    const int g  = lane >> 2;
    const int c2 = (lane & 3) << 1;

    const uint32_t sbase = (uint32_t)__cvta_generic_to_shared(smem);
    // ldmatrix per-lane byte offsets within one array (validated in R7)
    const uint32_t laneA = (uint32_t)(((warpM + ((lane >> 3) & 1) * 8 + (lane & 7)) * BKP
                                      + (lane >> 4) * 8) * 2);
    const uint32_t laneB = (uint32_t)(((warpN + ((lane >> 3) >> 1) * 8 + (lane & 7)) * BKP
                                      + ((lane >> 3) & 1) * 8) * 2);

    // fill coords: per array 512 16B-units; this thread owns units
    // (r0, q) and (r0+64, q) where r0 = tid>>2, q = tid&3.
    const int r0 = tid >> 2;
    const int qq = tid & 3;
    const int smoff0 = (r0 * BKP + qq * 8) * 2;          // bytes within array
    const int smoff1 = ((r0 + 64) * BKP + qq * 8) * 2;

    float acc[4][4][4];
#pragma unroll
    for (int mt = 0; mt < 4; ++mt)
#pragma unroll
        for (int nt = 0; nt < 4; ++nt)
#pragma unroll
            for (int r = 0; r < 4; ++r) acc[mt][nt][r] = 0.0f;

    uint4 rg[8];                                         // 4 arrays x 2 units

    auto prefetch = [&](int k0) {
        const size_t cA0 = (size_t)(m0 + r0) * lda + k0 + qq * 8;
        const size_t cA1 = (size_t)(m0 + r0 + 64) * lda + k0 + qq * 8;
        const size_t cB0 = (size_t)(n0 + r0) * ldb + k0 + qq * 8;
        const size_t cB1 = (size_t)(n0 + r0 + 64) * ldb + k0 + qq * 8;
        rg[0] = *(const uint4*)(Ah + cA0);
        rg[1] = *(const uint4*)(Ah + cA1);
        rg[2] = *(const uint4*)(Al + cA0);
        rg[3] = *(const uint4*)(Al + cA1);
        rg[4] = *(const uint4*)(Bh + cB0);
        rg[5] = *(const uint4*)(Bh + cB1);
        rg[6] = *(const uint4*)(Bl + cB0);
        rg[7] = *(const uint4*)(Bl + cB1);
    };
    auto store_stage = [&](int s) {
        unsigned char* sb = smem + s * STG_B;
#pragma unroll
        for (int arr = 0; arr < 4; ++arr) {
            *(uint4*)(sb + arr * ARR_B + smoff0) = rg[arr * 2 + 0];
            *(uint4*)(sb + arr * ARR_B + smoff1) = rg[arr * 2 + 1];
        }
    };

    prefetch(0);
    store_stage(0);
    __syncthreads();

    for (int it = 0; it < NT; ++it) {
        const int s = it & 1;
        // prefetch next chunk into regs (in flight during compute)
        if (it + 1 < NT) prefetch((it + 1) << 5);

        const uint32_t aHi = sbase + (uint32_t)(s * STG_B) + laneA;
        const uint32_t aLo = aHi + ARR_B;
        const uint32_t bHi = sbase + (uint32_t)(s * STG_B + 2 * ARR_B) + laneB;
        const uint32_t bLo = bHi + ARR_B;

#pragma unroll
        for (int ks = 0; ks < 2; ++ks) {
            const uint32_t kboff = (uint32_t)(ks * 16 * 2);
            unsigned ah[4][4], bh[4][2], al[4][4], bl[4][2];
#pragma unroll
            for (int mt = 0; mt < 4; ++mt)
                ldm_x4(ah[mt], aHi + (uint32_t)(mt * 16 * BKP * 2) + kboff);
#pragma unroll
            for (int p = 0; p < 2; ++p) {
                unsigned t[4];
                ldm_x4(t, bHi + (uint32_t)(p * 16 * BKP * 2) + kboff);
                bh[2 * p][0] = t[0]; bh[2 * p][1] = t[1];
                bh[2 * p + 1][0] = t[2]; bh[2 * p + 1][1] = t[3];
            }
#pragma unroll
            for (int mt = 0; mt < 4; ++mt)
#pragma unroll
                for (int nt = 0; nt < 4; ++nt)
                    mma_bf16(acc[mt][nt], ah[mt], bh[nt]);

#pragma unroll
            for (int mt = 0; mt < 4; ++mt)
                ldm_x4(al[mt], aLo + (uint32_t)(mt * 16 * BKP * 2) + kboff);
#pragma unroll
            for (int mt = 0; mt < 4; ++mt)
#pragma unroll
                for (int nt = 0; nt < 4; ++nt)
                    mma_bf16(acc[mt][nt], al[mt], bh[nt]);

#pragma unroll
            for (int p = 0; p < 2; ++p) {
                unsigned t[4];
                ldm_x4(t, bLo + (uint32_t)(p * 16 * BKP * 2) + kboff);
                bl[2 * p][0] = t[0]; bl[2 * p][1] = t[1];
                bl[2 * p + 1][0] = t[2]; bl[2 * p + 1][1] = t[3];
            }
#pragma unroll
            for (int mt = 0; mt < 4; ++mt)
#pragma unroll
                for (int nt = 0; nt < 4; ++nt)
                    mma_bf16(acc[mt][nt], ah[mt], bl[nt]);
        }

        // stage next chunk into the other buffer; its previous consumers
        // finished before the sync at the end of the previous iteration.
        if (it + 1 < NT) store_stage(s ^ 1);
        __syncthreads();
    }

    // ---- epilogue ----
    const float scale = (mode == 1) ? 0.03125f : 1.0f;
#pragma unroll
    for (int mt = 0; mt < 4; ++mt) {
        const int mr = m0 + warpM + mt * 16 + g;
#pragma unroll
        for (int nt = 0; nt < 4; ++nt) {
            const int nc = n0 + warpN + nt * 8 + c2;
            float* cc = acc[mt][nt];
            if (mode == 3) {                   // transposed bf16 hi/lo + bias (Vt)
                float b0 = bias[nc], b1 = bias[nc + 1];
                float v00 = cc[0] + b0, v01 = cc[1] + b1;
                float v10 = cc[2] + b0, v11 = cc[3] + b1;
                bf16 h00 = __float2bfloat16_rn(v00), h01 = __float2bfloat16_rn(v01);
                bf16 h10 = __float2bfloat16_rn(v10), h11 = __float2bfloat16_rn(v11);
                size_t o0 = (size_t)nc * ldc + mr, o1 = (size_t)(nc + 1) * ldc + mr;
                Chi[o0] = h00;      Chi[o1] = h01;
                Chi[o0 + 8] = h10;  Chi[o1 + 8] = h11;
                Clo[o0]     = __float2bfloat16_rn(v00 - __bfloat162float(h00));
                Clo[o1]     = __float2bfloat16_rn(v01 - __bfloat162float(h01));
                Clo[o0 + 8] = __float2bfloat16_rn(v10 - __bfloat162float(h10));
                Clo[o1 + 8] = __float2bfloat16_rn(v11 - __bfloat162float(h11));
            } else if (mode == 0) {            // bf16 hi/lo + bias
                float b0 = bias[nc], b1 = bias[nc + 1];
                float v00 = cc[0] + b0, v01 = cc[1] + b1;
                float v10 = cc[2] + b0, v11 = cc[3] + b1;
                __nv_bfloat162 h0 = __floats2bfloat162_rn(v00, v01);
                __nv_bfloat162 h1 = __floats2bfloat162_rn(v10, v11);
                size_t o0 = (size_t)mr * ldc + nc, o1 = (size_t)(mr + 8) * ldc + nc;
                *(__nv_bfloat162*)&Chi[o0] = h0;
                *(__nv_bfloat162*)&Chi[o1] = h1;
                __nv_bfloat162 l0 = __floats2bfloat162_rn(v00 - __bfloat162float(h0.x),
                                                          v01 - __bfloat162float(h0.y));
                __nv_bfloat162 l1 = __floats2bfloat162_rn(v10 - __bfloat162float(h1.x),
                                                          v11 - __bfloat162float(h1.y));
                *(__nv_bfloat162*)&Clo[o0] = l0;
                *(__nv_bfloat162*)&Clo[o1] = l1;
            } else {                           // fp32 (mode 1 scaled, mode 2 plain)
                *(float2*)&Cf[(size_t)mr * ldc + nc] =
                    make_float2(cc[0] * scale, cc[1] * scale);
                *(float2*)&Cf[(size_t)(mr + 8) * ldc + nc] =
                    make_float2(cc[2] * scale, cc[3] * scale);
            }
        }
    }
}

// ---------------------------------------------------------------------------
// fp32 -> bf16 hi/lo split (elementwise, vectorized by 4)
// ---------------------------------------------------------------------------
__global__ void __launch_bounds__(256)
cvt_split(const float* __restrict__ x, bf16* __restrict__ hi, bf16* __restrict__ lo, int n4)
{
    int i = blockIdx.x * 256 + threadIdx.x;
    if (i >= n4) return;
    float4 v = ((const float4*)x)[i];
    float a[4] = { v.x, v.y, v.z, v.w };
    bf16 h[4]; bf16 l[4];
#pragma unroll
    for (int e = 0; e < 4; ++e) {
        h[e] = __float2bfloat16_rn(a[e]);
        l[e] = __float2bfloat16_rn(a[e] - __bfloat162float(h[e]));
    }
    ((ushort4*)hi)[i] = make_ushort4(*(unsigned short*)&h[0], *(unsigned short*)&h[1],
                                     *(unsigned short*)&h[2], *(unsigned short*)&h[3]);
    ((ushort4*)lo)[i] = make_ushort4(*(unsigned short*)&l[0], *(unsigned short*)&l[1],
                                     *(unsigned short*)&l[2], *(unsigned short*)&l[3]);
}

// ---------------------------------------------------------------------------
// Causal row softmax: reads S fp32, writes P as bf16 hi/lo (zeros in masked
// tail of the diagonal block so PV needs no per-element mask).
// ---------------------------------------------------------------------------
__global__ void __launch_bounds__(256)
softmax_kernel(const float* __restrict__ Sc, bf16* __restrict__ Ph, bf16* __restrict__ Pl)
{
    const int row = blockIdx.x;
    const int q   = row & (SEQ - 1);
    const float* r = Sc + (size_t)row * SEQ;
    const int kend = ((q >> 7) + 1) << 7;
    const int tid = threadIdx.x;

    float vals[8];
    float mx = -INFINITY;
    {
        int it = 0;
        for (int j = tid; j < kend; j += 256, ++it) {
            float v = (j <= q) ? r[j] : -INFINITY;
            vals[it] = v;
            mx = fmaxf(mx, v);
        }
    }

    __shared__ float red[8];
#pragma unroll
    for (int o = 16; o > 0; o >>= 1) mx = fmaxf(mx, __shfl_xor_sync(0xffffffffu, mx, o));
    if ((tid & 31) == 0) red[tid >> 5] = mx;
    __syncthreads();
    if (tid == 0) {
        float m = red[0];
#pragma unroll
        for (int i = 1; i < 8; ++i) m = fmaxf(m, red[i]);
        red[0] = m;
    }
    __syncthreads();
    mx = red[0];
    __syncthreads();

    float sum = 0.0f;
    {
        int it = 0;
        for (int j = tid; j < kend; j += 256, ++it) {
            float e = __expf(vals[it] - mx);
            vals[it] = e;
            sum += e;
        }
    }
#pragma unroll
    for (int o = 16; o > 0; o >>= 1) sum += __shfl_xor_sync(0xffffffffu, sum, o);
    if ((tid & 31) == 0) red[tid >> 5] = sum;
    __syncthreads();
    if (tid == 0) {
        float s = red[0];
#pragma unroll
        for (int i = 1; i < 8; ++i) s += red[i];
        red[0] = s;
    }
    __syncthreads();
    const float inv = 1.0f / red[0];

    {
        bf16* ph = Ph + (size_t)row * SEQ;
        bf16* pl = Pl + (size_t)row * SEQ;
        int it = 0;
        for (int j = tid; j < kend; j += 256, ++it) {
            float p = vals[it] * inv;
            bf16 h = __float2bfloat16_rn(p);
            ph[j] = h;
            pl[j] = __float2bfloat16_rn(p - __bfloat162float(h));
        }
    }
}

// ---------------------------------------------------------------------------
// Launch. Inputs: x, Wq, bq, Wk, bk, Wv, bv, mask (mask = known tril, ignored).
// ---------------------------------------------------------------------------
extern "C" void kernel_launch(void* const* d_in, const int* in_sizes, int n_in,
                              void* d_out, int out_size)
{
    const float* x  = (const float*)d_in[0];
    const float* Wq = (const float*)d_in[1];
    const float* bq = (const float*)d_in[2];
    const float* Wk = (const float*)d_in[3];
    const float* bk = (const float*)d_in[4];
    const float* Wv = (const float*)d_in[5];
    const float* bv = (const float*)d_in[6];
    float* out = (float*)d_out;

    bf16 *xh, *xl, *Wqh, *Wql, *Wkh, *Wkl, *Wvh, *Wvl;
    bf16 *Qh, *Ql, *Kh, *Kl, *Vth, *Vtl, *Ph, *Pl;
    float *Sc;
    cudaGetSymbolAddress((void**)&xh,  g_xh);   cudaGetSymbolAddress((void**)&xl,  g_xl);
    cudaGetSymbolAddress((void**)&Wqh, g_Wqh);  cudaGetSymbolAddress((void**)&Wql, g_Wql);
    cudaGetSymbolAddress((void**)&Wkh, g_Wkh);  cudaGetSymbolAddress((void**)&Wkl, g_Wkl);
    cudaGetSymbolAddress((void**)&Wvh, g_Wvh);  cudaGetSymbolAddress((void**)&Wvl, g_Wvl);
    cudaGetSymbolAddress((void**)&Qh,  g_Qh);   cudaGetSymbolAddress((void**)&Ql,  g_Ql);
    cudaGetSymbolAddress((void**)&Kh,  g_Kh);   cudaGetSymbolAddress((void**)&Kl,  g_Kl);
    cudaGetSymbolAddress((void**)&Vth, g_Vth);  cudaGetSymbolAddress((void**)&Vtl, g_Vtl);
    cudaGetSymbolAddress((void**)&Ph,  g_Ph);   cudaGetSymbolAddress((void**)&Pl,  g_Pl);
    cudaGetSymbolAddress((void**)&Sc,  g_S);

    cudaFuncSetAttribute(mma_gemm_nt, cudaFuncAttributeMaxDynamicSharedMemorySize, SMEM_TOT);

    dim3 blk(256);

    // 0) split fp32 -> bf16 hi/lo for x and weights
    cvt_split<<<(MTOT * EMB / 4 + 255) / 256, blk>>>(x,  xh,  xl,  MTOT * EMB / 4);
    cvt_split<<<(EMB * EMB / 4 + 255) / 256, blk>>>(Wq, Wqh, Wql, EMB * EMB / 4);
    cvt_split<<<(EMB * EMB / 4 + 255) / 256, blk>>>(Wk, Wkh, Wkl, EMB * EMB / 4);
    cvt_split<<<(EMB * EMB / 4 + 255) / 256, blk>>>(Wv, Wvh, Wvl, EMB * EMB / 4);

    // 1) QKV projections (NT): Q,K -> bf16 hi/lo; V -> transposed bf16 hi/lo
    dim3 gQKV(EMB / 128, MTOT / 128, 1);
    mma_gemm_nt<<<gQKV, blk, SMEM_TOT>>>(xh, xl, Wqh, Wql, nullptr, Qh, Ql, bq,
                                         EMB, EMB, EMB, EMB, 0, 0, 0, 0);
    mma_gemm_nt<<<gQKV, blk, SMEM_TOT>>>(xh, xl, Wkh, Wkl, nullptr, Kh, Kl, bk,
                                         EMB, EMB, EMB, EMB, 0, 0, 0, 0);
    mma_gemm_nt<<<gQKV, blk, SMEM_TOT>>>(xh, xl, Wvh, Wvl, nullptr, Vth, Vtl, bv,
                                         EMB, EMB, MTOT, EMB, 3, 0, 0, 0);

    // 2) scores = Q K^T / 32 (NT, causal skip, batched)
    dim3 gS(SEQ / 128, SEQ / 128, BATCH);
    mma_gemm_nt<<<gS, blk, SMEM_TOT>>>(Qh, Ql, Kh, Kl, Sc, nullptr, nullptr, nullptr,
                                       EMB, EMB, SEQ, EMB, 1,
                                       (size_t)SEQ * EMB, (size_t)SEQ * EMB, (size_t)SEQ * SEQ);

    // 3) causal softmax -> P bf16 hi/lo
    softmax_kernel<<<BATCH * SEQ, blk>>>(Sc, Ph, Pl);

    // 4) out = P V  (NT against Vt, k-bounded, batched)
    dim3 gPV(EMB / 128, SEQ / 128, BATCH);
    mma_gemm_nt<<<gPV, blk, SMEM_TOT>>>(Ph, Pl, Vth, Vtl, out, nullptr, nullptr, nullptr,
                                        SEQ, MTOT, EMB, SEQ, 2,
                                        (size_t)SEQ * SEQ, (size_t)SEQ, (size_t)SEQ * EMB);
}